// round 1
// baseline (speedup 1.0000x reference)
#include <cuda_runtime.h>

// Problem constants (fixed by the dataset)
#define IN_F   128
#define OUT_F  64
#define N_DIV  4
#define N_MAX  100000

// Scratch: t[d][n][o] = norm[n] * (feature[n] . W[d][o]),  [4, N, 64] f32 = 102.4 MB
__device__ float t_buf[(size_t)N_DIV * N_MAX * OUT_F];

__device__ __forceinline__ void fma2(unsigned long long &c,
                                     unsigned long long a,
                                     unsigned long long b) {
    asm("fma.rn.f32x2 %0, %1, %2, %0;" : "+l"(c) : "l"(a), "l"(b));
}
__device__ __forceinline__ float2 unpack2(unsigned long long v) {
    float2 r;
    asm("mov.b64 {%0, %1}, %2;" : "=f"(r.x), "=f"(r.y) : "l"(v));
    return r;
}

// ---------------------------------------------------------------------------
// Kernel 1: per-division GEMM.  Tile: 64 nodes x 64 outs (one division per
// blockIdx.y), K=128 in two 64-wide phases. 256 threads, 4x4 microtile per
// thread, accumulators are f32x2 pairs packed over the K dimension.
// ---------------------------------------------------------------------------
__global__ void __launch_bounds__(256, 2) gemm_kernel(
    const float* __restrict__ feat,   // [N, 128]
    const float* __restrict__ W,      // [4, 64, 128]
    const float* __restrict__ norm,   // [N]
    int N)
{
    __shared__ __align__(16) float As[64 * 64];   // feature tile, XOR-swizzled rows
    __shared__ __align__(16) float Bs[64 * 64];   // W tile, XOR-swizzled rows

    const int d    = blockIdx.y;
    const int n0   = blockIdx.x * 64;
    const int tid  = threadIdx.x;
    const int lane = tid & 31;
    const int wrp  = tid >> 5;
    const int tx   = lane & 15;                 // out-group   (0..15)
    const int ty   = (wrp << 1) | (lane >> 4);  // node-group  (0..15)

    unsigned long long acc[4][4];
    #pragma unroll
    for (int i = 0; i < 4; ++i)
        #pragma unroll
        for (int j = 0; j < 4; ++j) acc[i][j] = 0ull;

    const float4* fsrc = (const float4*)feat;
    const float4* wsrc = (const float4*)(W + (size_t)d * OUT_F * IN_F);

    const int sa = (ty & 7) << 2;   // swizzle key for A loads (in float units *4 below)
    const int sb = (tx & 7) << 2;

    for (int kt = 0; kt < 2; ++kt) {
        __syncthreads();
        // load 64 rows x 16 float4 into each of As / Bs, swizzled within row
        #pragma unroll
        for (int i = tid; i < 1024; i += 256) {
            int r  = i >> 4;
            int k4 = i & 15;
            int ks = k4 ^ ((r >> 2) & 7);
            int n  = n0 + r;
            float4 av = (n < N) ? fsrc[(size_t)n * 32 + kt * 16 + k4]
                                : make_float4(0.f, 0.f, 0.f, 0.f);
            *(float4*)&As[r * 64 + ks * 4] = av;
            *(float4*)&Bs[r * 64 + ks * 4] = wsrc[r * 32 + kt * 16 + k4];
        }
        __syncthreads();

        #pragma unroll
        for (int k4 = 0; k4 < 16; ++k4) {
            ulonglong2 a[4], b[4];
            #pragma unroll
            for (int i = 0; i < 4; ++i)
                a[i] = *(const ulonglong2*)&As[(ty * 4 + i) * 64 + (((k4 << 2) ^ sa))];
            #pragma unroll
            for (int j = 0; j < 4; ++j)
                b[j] = *(const ulonglong2*)&Bs[(tx * 4 + j) * 64 + (((k4 << 2) ^ sb))];
            #pragma unroll
            for (int i = 0; i < 4; ++i)
                #pragma unroll
                for (int j = 0; j < 4; ++j) {
                    fma2(acc[i][j], a[i].x, b[j].x);
                    fma2(acc[i][j], a[i].y, b[j].y);
                }
        }
    }

    // epilogue: reduce the k-even/k-odd partial sums, scale by norm[n], store
    #pragma unroll
    for (int i = 0; i < 4; ++i) {
        int n = n0 + ty * 4 + i;
        if (n < N) {
            float nm = norm[n];
            float2 v0 = unpack2(acc[i][0]);
            float2 v1 = unpack2(acc[i][1]);
            float2 v2 = unpack2(acc[i][2]);
            float2 v3 = unpack2(acc[i][3]);
            float4 r;
            r.x = (v0.x + v0.y) * nm;
            r.y = (v1.x + v1.y) * nm;
            r.z = (v2.x + v2.y) * nm;
            r.w = (v3.x + v3.y) * nm;
            *(float4*)&t_buf[((size_t)d * N + n) * OUT_F + tx * 4] = r;
        }
    }
}

// ---------------------------------------------------------------------------
// Kernel 2: edge scatter. 64 threads per edge (one per output feature).
// out is pre-zeroed; out[dst*256 + div*64 + o] += t[div][src][o]
// ---------------------------------------------------------------------------
__global__ void scatter_kernel(const int* __restrict__ src,
                               const int* __restrict__ dst,
                               const int* __restrict__ ediv,
                               float* __restrict__ out,
                               int E, int N)
{
    int idx = blockIdx.x * blockDim.x + threadIdx.x;
    int e = idx >> 6;
    if (e >= E) return;
    int o  = idx & 63;
    int s  = src[e];
    int dd = dst[e];
    int dv = ediv[e];
    float v = t_buf[((size_t)dv * N + s) * OUT_F + o];
    atomicAdd(&out[(size_t)dd * (N_DIV * OUT_F) + dv * OUT_F + o], v);
}

// ---------------------------------------------------------------------------
// Kernel 3: h = relu(agg * norm[n]), in place on d_out, float4-vectorized
// ---------------------------------------------------------------------------
__global__ void finalize_kernel(const float* __restrict__ norm,
                                float* __restrict__ out, int N)
{
    int idx = blockIdx.x * blockDim.x + threadIdx.x;   // over N*64 float4s
    if (idx >= N * 64) return;
    int n = idx >> 6;
    float nm = norm[n];
    float4* o4 = (float4*)out;
    float4 v = o4[idx];
    v.x = fmaxf(v.x * nm, 0.f);
    v.y = fmaxf(v.y * nm, 0.f);
    v.z = fmaxf(v.z * nm, 0.f);
    v.w = fmaxf(v.w * nm, 0.f);
    o4[idx] = v;
}

// ---------------------------------------------------------------------------
extern "C" void kernel_launch(void* const* d_in, const int* in_sizes, int n_in,
                              void* d_out, int out_size)
{
    const float* feat = (const float*)d_in[0];
    const float* W    = (const float*)d_in[1];
    const float* norm = (const float*)d_in[2];
    const int*   src  = (const int*)d_in[3];
    const int*   dst  = (const int*)d_in[4];
    const int*   ediv = (const int*)d_in[5];
    float*       out  = (float*)d_out;

    const int N = in_sizes[2];   // 100000
    const int E = in_sizes[3];   // 1600000

    // zero the aggregation buffer (d_out is poisoned)
    cudaMemsetAsync(d_out, 0, (size_t)out_size * sizeof(float), 0);

    // 1) t[d][n][o] = norm[n] * feature[n] . W[d][o]
    dim3 g1((N + 63) / 64, N_DIV);
    gemm_kernel<<<g1, 256>>>(feat, W, norm, N);

    // 2) scatter-add over edges
    long long total = (long long)E * 64;
    int blocks = (int)((total + 255) / 256);
    scatter_kernel<<<blocks, 256>>>(src, dst, ediv, out, E, N);

    // 3) final norm scale + relu
    int fb = (N * 64 + 255) / 256;
    finalize_kernel<<<fb, 256>>>(norm, out, N);
}